// round 9
// baseline (speedup 1.0000x reference)
#include <cuda_runtime.h>

// Problem constants
#define PB 32
#define PM 32768
#define PD 128
#define PR 64
#define PW (2 * PR + 1)   // 129

#define VEC_PER_ROW (PD / 4)               // 32
#define VEC_PER_BATCH (PM * VEC_PER_ROW)   // 2^20
#define TOTAL_VEC (PB * VEC_PER_BATCH)     // 2^25
#define UNROLL 2
#define THREADS 256
#define BLOCKS (TOTAL_VEC / (THREADS * UNROLL))   // 65536
#define STRIDE (THREADS * BLOCKS)                 // 2^24

__device__ __forceinline__ float4 ldcs4(const float4* p) {
    float4 v;
    asm volatile("ld.global.cs.v4.f32 {%0,%1,%2,%3}, [%4];"
                 : "=f"(v.x), "=f"(v.y), "=f"(v.z), "=f"(v.w) : "l"(p));
    return v;
}
__device__ __forceinline__ void stcs4(float4* p, float4 v) {
    asm volatile("st.global.cs.v4.f32 [%0], {%1,%2,%3,%4};"
                 :: "l"(p), "f"(v.x), "f"(v.y), "f"(v.z), "f"(v.w));
}

__global__ __launch_bounds__(THREADS)
void ring_write_kernel(const float4* __restrict__ ring,
                       const float4* __restrict__ write_vec,   // [B, D/4]
                       const float* __restrict__ weights,      // [B, W]
                       const float* __restrict__ erase,        // [B]
                       const float* __restrict__ gate,         // [B]
                       const int* __restrict__ idx,            // [B, W]
                       float4* __restrict__ out)
{
    int t0 = blockIdx.x * THREADS + threadIdx.x;

    // Two independent streams, STRIDE apart — back-to-back LDG.128 (MLP=2)
    int t1 = t0 + STRIDE;

    float4 v0 = ldcs4(&ring[t0]);
    float4 v1 = ldcs4(&ring[t1]);

    #pragma unroll
    for (int u = 0; u < UNROLL; u++) {
        int t = (u == 0) ? t0 : t1;
        float4 v = (u == 0) ? v0 : v1;

        int b   = t >> 20;                 // / VEC_PER_BATCH
        int rem = t & (VEC_PER_BATCH - 1);
        int m   = rem >> 5;                // row within ring
        int c   = rem & (VEC_PER_ROW - 1); // float4 within row

        int start = __ldg(&idx[b * PW]);   // window start for this batch
        int j = m - start;
        if (j < 0) j += PM;

        if (j < PW) {
            float w = __ldg(&weights[b * PW + j]);
            float e = __ldg(&erase[b]);
            float g = __ldg(&gate[b]);
            float a  = 1.0f - e * w;
            float gw = g * w;
            float4 wv = __ldg(&write_vec[b * VEC_PER_ROW + c]);
            v.x = v.x * a + gw * wv.x;
            v.y = v.y * a + gw * wv.y;
            v.z = v.z * a + gw * wv.z;
            v.w = v.w * a + gw * wv.w;
        }

        stcs4(&out[t], v);
    }
}

extern "C" void kernel_launch(void* const* d_in, const int* in_sizes, int n_in,
                              void* d_out, int out_size)
{
    const float4* ring      = (const float4*)d_in[0];
    const float4* write_vec = (const float4*)d_in[1];
    const float*  weights   = (const float*)d_in[2];
    const float*  erase     = (const float*)d_in[3];
    const float*  gate      = (const float*)d_in[4];
    const int*    idx       = (const int*)d_in[5];
    float4*       out       = (float4*)d_out;

    ring_write_kernel<<<BLOCKS, THREADS>>>(ring, write_vec, weights, erase, gate, idx, out);
}

// round 10
// speedup vs baseline: 1.0105x; 1.0105x over previous
#include <cuda_runtime.h>

// Problem constants
#define PB 32
#define PM 32768
#define PD 128
#define PR 64
#define PW (2 * PR + 1)   // 129

#define VEC_PER_ROW (PD / 4)               // 32
#define VEC_PER_BATCH (PM * VEC_PER_ROW)   // 2^20
#define TOTAL_VEC (PB * VEC_PER_BATCH)     // 2^25
#define UNROLL 3
#define THREADS 256
// ceil(TOTAL_VEC / (THREADS*UNROLL)) = ceil(2^25/768) = 43691
#define BLOCKS ((TOTAL_VEC + THREADS * UNROLL - 1) / (THREADS * UNROLL))
#define STRIDE (THREADS * BLOCKS)          // 11184896

__device__ __forceinline__ float4 ldcs4(const float4* p) {
    float4 v;
    asm volatile("ld.global.cs.v4.f32 {%0,%1,%2,%3}, [%4];"
                 : "=f"(v.x), "=f"(v.y), "=f"(v.z), "=f"(v.w) : "l"(p));
    return v;
}
__device__ __forceinline__ void stcs4(float4* p, float4 v) {
    asm volatile("st.global.cs.v4.f32 [%0], {%1,%2,%3,%4};"
                 :: "l"(p), "f"(v.x), "f"(v.y), "f"(v.z), "f"(v.w));
}

__global__ __launch_bounds__(THREADS)
void ring_write_kernel(const float4* __restrict__ ring,
                       const float4* __restrict__ write_vec,   // [B, D/4]
                       const float* __restrict__ weights,      // [B, W]
                       const float* __restrict__ erase,        // [B]
                       const float* __restrict__ gate,         // [B]
                       const int* __restrict__ idx,            // [B, W]
                       float4* __restrict__ out)
{
    int t0 = blockIdx.x * THREADS + threadIdx.x;

    int    t[UNROLL];
    float4 v[UNROLL];

    // Three independent streams, STRIDE apart — front-batched LDG.128 (MLP=3)
    #pragma unroll
    for (int u = 0; u < UNROLL; u++) {
        t[u] = t0 + u * STRIDE;
        if (t[u] < TOTAL_VEC) v[u] = ldcs4(&ring[t[u]]);
    }

    #pragma unroll
    for (int u = 0; u < UNROLL; u++) {
        int tt = t[u];
        if (tt >= TOTAL_VEC) continue;

        int b   = tt >> 20;                 // / VEC_PER_BATCH
        int rem = tt & (VEC_PER_BATCH - 1);
        int m   = rem >> 5;                 // row within ring
        int c   = rem & (VEC_PER_ROW - 1);  // float4 within row

        int start = __ldg(&idx[b * PW]);    // window start for this batch
        int j = m - start;
        if (j < 0) j += PM;

        float4 vv = v[u];
        if (j < PW) {
            float w = __ldg(&weights[b * PW + j]);
            float e = __ldg(&erase[b]);
            float g = __ldg(&gate[b]);
            float a  = 1.0f - e * w;
            float gw = g * w;
            float4 wv = __ldg(&write_vec[b * VEC_PER_ROW + c]);
            vv.x = vv.x * a + gw * wv.x;
            vv.y = vv.y * a + gw * wv.y;
            vv.z = vv.z * a + gw * wv.z;
            vv.w = vv.w * a + gw * wv.w;
        }

        stcs4(&out[tt], vv);
    }
}

extern "C" void kernel_launch(void* const* d_in, const int* in_sizes, int n_in,
                              void* d_out, int out_size)
{
    const float4* ring      = (const float4*)d_in[0];
    const float4* write_vec = (const float4*)d_in[1];
    const float*  weights   = (const float*)d_in[2];
    const float*  erase     = (const float*)d_in[3];
    const float*  gate      = (const float*)d_in[4];
    const int*    idx       = (const int*)d_in[5];
    float4*       out       = (float4*)d_out;

    ring_write_kernel<<<BLOCKS, THREADS>>>(ring, write_vec, weights, erase, gate, idx, out);
}